// round 1
// baseline (speedup 1.0000x reference)
#include <cuda_runtime.h>

#define NUM_USERS 100000
#define NUM_ITEMS 50000
#define NN        (NUM_USERS + NUM_ITEMS)   // 150000
#define EMB       64
#define NBIC      20000

// ---------------- static device scratch (allocation-free rule) ----------------
__device__ __align__(16) float g_e0[NN * EMB];          // 38.4 MB
__device__ __align__(16) float g_e1[NN * EMB];          // 38.4 MB
__device__ __align__(16) float g_bic[NBIC * EMB];       // 5.12 MB
__device__ __align__(16) float g_ul[NUM_USERS * EMB];   // 25.6 MB
__device__ __align__(16) float g_dhv[NBIC];
__device__ __align__(16) float g_dhu[NUM_USERS];

// ---------------- kernels ----------------

// e0 = concat(user, item); acc(d_out) = same
__global__ void k_init(const float4* __restrict__ u, const float4* __restrict__ it,
                       float4* __restrict__ e0, float4* __restrict__ acc) {
    int i = blockIdx.x * blockDim.x + threadIdx.x;
    const int n4u = NUM_USERS * (EMB / 4);
    const int n4  = NN * (EMB / 4);
    if (i >= n4) return;
    float4 v = (i < n4u) ? u[i] : it[i - n4u];
    e0[i]  = v;
    acc[i] = v;
}

__global__ void k_zero(float4* __restrict__ p, int n4) {
    int i = blockIdx.x * blockDim.x + threadIdx.x;
    if (i < n4) p[i] = make_float4(0.f, 0.f, 0.f, 0.f);
}

// y[row[e]] += val[e] * x[col[e]]  — 16 threads per edge, float4 gather, 4 scalar atomics
__global__ void k_spmm(const int* __restrict__ row, const int* __restrict__ col,
                       const float* __restrict__ val, const float4* __restrict__ x,
                       float* __restrict__ y, int ne) {
    int t = blockIdx.x * blockDim.x + threadIdx.x;
    int e = t >> 4;
    if (e >= ne) return;
    int g = t & 15;
    int r = row[e];
    int c = col[e];
    float v = val[e];
    float4 xv = x[c * 16 + g];
    float* yp = y + (r * EMB + g * 4);
    atomicAdd(yp + 0, v * xv.x);
    atomicAdd(yp + 1, v * xv.y);
    atomicAdd(yp + 2, v * xv.z);
    atomicAdd(yp + 3, v * xv.w);
}

__global__ void k_add(float4* __restrict__ acc, const float4* __restrict__ e, int n4) {
    int i = blockIdx.x * blockDim.x + threadIdx.x;
    if (i >= n4) return;
    float4 a = acc[i], b = e[i];
    a.x += b.x; a.y += b.y; a.z += b.z; a.w += b.w;
    acc[i] = a;
}

__global__ void k_deg(const int* __restrict__ row, const float* __restrict__ val,
                      float* __restrict__ deg, int ne) {
    int i = blockIdx.x * blockDim.x + threadIdx.x;
    if (i < ne) atomicAdd(&deg[row[i]], val[i]);
}

// bic[r] /= max(deg[r], deg==0 -> 1)
__global__ void k_norm(float4* __restrict__ bic, const float* __restrict__ deg, int nrows) {
    int i = blockIdx.x * blockDim.x + threadIdx.x;
    int n4 = nrows * (EMB / 4);
    if (i >= n4) return;
    int r = i >> 4;
    float d = deg[r];
    float inv = (d == 0.f) ? 1.f : (1.f / d);
    float4 b = bic[i];
    b.x *= inv; b.y *= inv; b.z *= inv; b.w *= inv;
    bic[i] = b;
}

// users: out = out*0.25 + ul/deg ; items: out *= 0.25
__global__ void k_final(float4* __restrict__ out, const float4* __restrict__ ul,
                        const float* __restrict__ dhu) {
    int i = blockIdx.x * blockDim.x + threadIdx.x;
    const int n4u = NUM_USERS * (EMB / 4);
    const int n4  = NN * (EMB / 4);
    if (i >= n4) return;
    float4 o = out[i];
    if (i < n4u) {
        int r = i >> 4;
        float d = dhu[r];
        float inv = (d == 0.f) ? 1.f : (1.f / d);
        float4 l = ul[i];
        o.x = o.x * 0.25f + l.x * inv;
        o.y = o.y * 0.25f + l.y * inv;
        o.z = o.z * 0.25f + l.z * inv;
        o.w = o.w * 0.25f + l.w * inv;
    } else {
        o.x *= 0.25f; o.y *= 0.25f; o.z *= 0.25f; o.w *= 0.25f;
    }
    out[i] = o;
}

// ---------------- launch ----------------
extern "C" void kernel_launch(void* const* d_in, const int* in_sizes, int n_in,
                              void* d_out, int out_size) {
    const float* user    = (const float*)d_in[0];
    const float* item    = (const float*)d_in[1];
    const float* adj_val = (const float*)d_in[2];
    const float* hv_val  = (const float*)d_in[3];
    const float* hu_val  = (const float*)d_in[4];
    const int*   adj_row = (const int*)d_in[5];
    const int*   adj_col = (const int*)d_in[6];
    const int*   hv_row  = (const int*)d_in[7];
    const int*   hv_col  = (const int*)d_in[8];
    const int*   hu_row  = (const int*)d_in[9];
    const int*   hu_col  = (const int*)d_in[10];
    float* out = (float*)d_out;

    const int E_adj = in_sizes[2];
    const int E_hv  = in_sizes[3];
    const int E_hu  = in_sizes[4];

    float *e0, *e1, *bic, *ul, *dhv, *dhu;
    cudaGetSymbolAddress((void**)&e0,  g_e0);
    cudaGetSymbolAddress((void**)&e1,  g_e1);
    cudaGetSymbolAddress((void**)&bic, g_bic);
    cudaGetSymbolAddress((void**)&ul,  g_ul);
    cudaGetSymbolAddress((void**)&dhv, g_dhv);
    cudaGetSymbolAddress((void**)&dhu, g_dhu);

    const int TB = 256;
    const int n4 = NN * (EMB / 4);  // 2.4M float4

    // init acc(d_out) and e0 with all_emb
    k_init<<<(n4 + TB - 1) / TB, TB>>>((const float4*)user, (const float4*)item,
                                       (float4*)e0, (float4*)out);

    // zero hyper-path buffers (independent; enqueue early)
    k_zero<<<(NBIC * 16 + TB - 1) / TB, TB>>>((float4*)bic, NBIC * 16);
    k_zero<<<(NUM_USERS * 16 + TB - 1) / TB, TB>>>((float4*)ul, NUM_USERS * 16);
    k_zero<<<(NBIC / 4 + TB - 1) / TB, TB>>>((float4*)dhv, NBIC / 4);
    k_zero<<<(NUM_USERS / 4 + TB - 1) / TB, TB>>>((float4*)dhu, NUM_USERS / 4);

    // 3 propagation layers: e_out = A * e_in ; acc += e_out
    float* ein  = e0;
    float* eout = e1;
    for (int l = 0; l < 3; l++) {
        k_zero<<<(n4 + TB - 1) / TB, TB>>>((float4*)eout, n4);
        int nt = E_adj * 16;
        k_spmm<<<(nt + TB - 1) / TB, TB>>>(adj_row, adj_col, adj_val,
                                           (const float4*)ein, eout, E_adj);
        k_add<<<(n4 + TB - 1) / TB, TB>>>((float4*)out, (const float4*)eout, n4);
        float* tmp = ein; ein = eout; eout = tmp;
    }

    // hyper path: biclique_feat = normalize(Hv * item_emb)
    k_deg<<<(E_hv + TB - 1) / TB, TB>>>(hv_row, hv_val, dhv, E_hv);
    {
        int nt = E_hv * 16;
        k_spmm<<<(nt + TB - 1) / TB, TB>>>(hv_row, hv_col, hv_val,
                                           (const float4*)item, bic, E_hv);
    }
    k_norm<<<(NBIC * 16 + TB - 1) / TB, TB>>>((float4*)bic, dhv, NBIC);

    // u_local_raw = Hu * biclique_feat
    k_deg<<<(E_hu + TB - 1) / TB, TB>>>(hu_row, hu_val, dhu, E_hu);
    {
        int nt = E_hu * 16;
        k_spmm<<<(nt + TB - 1) / TB, TB>>>(hu_row, hu_col, hu_val,
                                           (const float4*)bic, ul, E_hu);
    }

    // out[users] = acc*0.25 + ul/deg ; out[items] = acc*0.25
    k_final<<<(n4 + TB - 1) / TB, TB>>>((float4*)out, (const float4*)ul, dhu);
}

// round 2
// speedup vs baseline: 2.3769x; 2.3769x over previous
#include <cuda_runtime.h>

#define NUM_USERS 100000
#define NUM_ITEMS 50000
#define NN        (NUM_USERS + NUM_ITEMS)   // 150000
#define EMB       64
#define NBIC      20000
#define E_ADJ_MAX 1200000
#define E_HV_MAX  400000
#define E_HU_MAX  400000

// ---------------- static device scratch ----------------
__device__ __align__(16) float g_ea[NN * EMB];          // layer-1 output (38.4MB)
__device__ __align__(16) float g_eb[NN * EMB];          // layer-2 output (38.4MB)
__device__ __align__(16) float g_bic[NBIC * EMB];       // biclique features

__device__ int  g_cnt_adj[NN];        // histogram -> cur (scatter cursor)
__device__ int  g_rp_adj[NN + 1];     // rowptr
__device__ int2 g_ep_adj[E_ADJ_MAX];  // packed (col, val-bits)

__device__ int  g_cnt_hv[NBIC];
__device__ int  g_rp_hv[NBIC + 1];
__device__ int2 g_ep_hv[E_HV_MAX];

__device__ int  g_cnt_hu[NUM_USERS];
__device__ int  g_rp_hu[NUM_USERS + 1];
__device__ int2 g_ep_hu[E_HU_MAX];

__device__ int  g_bsum[256];          // reused by the three scans (stream-serial)

// ---------------- CSR build ----------------

__global__ void k_zero_cnt() {
    int i = blockIdx.x * blockDim.x + threadIdx.x;
    if (i < NN)        g_cnt_adj[i] = 0;
    if (i < NBIC)      g_cnt_hv[i]  = 0;
    if (i < NUM_USERS) g_cnt_hu[i]  = 0;
}

__global__ void k_hist(const int* __restrict__ row, int ne, int* __restrict__ cnt) {
    int i = blockIdx.x * blockDim.x + threadIdx.x;
    if (i < ne) atomicAdd(&cnt[row[i]], 1);
}

// block of 256 threads sums 1024 elements
__global__ void k_blocksum(const int* __restrict__ cnt, int n, int* __restrict__ bsum) {
    __shared__ int sm[256];
    int t = threadIdx.x;
    int base = blockIdx.x * 1024 + t * 4;
    int s = 0;
    #pragma unroll
    for (int i = 0; i < 4; i++) { int idx = base + i; if (idx < n) s += cnt[idx]; }
    sm[t] = s; __syncthreads();
    for (int o = 128; o > 0; o >>= 1) {
        if (t < o) sm[t] += sm[t + o];
        __syncthreads();
    }
    if (t == 0) bsum[blockIdx.x] = sm[0];
}

// single block: exclusive scan of nb (<=256) block sums
__global__ void k_scan_bsum(int* __restrict__ bsum, int nb) {
    __shared__ int sm[256];
    int t = threadIdx.x;
    int v = (t < nb) ? bsum[t] : 0;
    sm[t] = v; __syncthreads();
    for (int o = 1; o < 256; o <<= 1) {
        int x = (t >= o) ? sm[t - o] : 0;
        __syncthreads();
        sm[t] += x;
        __syncthreads();
    }
    if (t < nb) bsum[t] = sm[t] - v;   // exclusive
}

// per-chunk exclusive scan + block offset; writes rowptr and cur (=rowptr copy)
__global__ void k_scan_chunk(int* __restrict__ cnt /*in: counts, out: cur*/,
                             int n, int ne,
                             const int* __restrict__ bsum,
                             int* __restrict__ rowptr) {
    __shared__ int sm[256];
    int t = threadIdx.x;
    int base = blockIdx.x * 1024 + t * 4;
    int c0 = 0, c1 = 0, c2 = 0, c3 = 0;
    if (base + 0 < n) c0 = cnt[base + 0];
    if (base + 1 < n) c1 = cnt[base + 1];
    if (base + 2 < n) c2 = cnt[base + 2];
    if (base + 3 < n) c3 = cnt[base + 3];
    int tot = c0 + c1 + c2 + c3;
    sm[t] = tot; __syncthreads();
    for (int o = 1; o < 256; o <<= 1) {
        int x = (t >= o) ? sm[t - o] : 0;
        __syncthreads();
        sm[t] += x;
        __syncthreads();
    }
    int pre = sm[t] - tot + bsum[blockIdx.x];   // exclusive prefix of this thread
    int p0 = pre, p1 = pre + c0, p2 = p1 + c1, p3 = p2 + c2;
    if (base + 0 < n) { rowptr[base + 0] = p0; cnt[base + 0] = p0; }
    if (base + 1 < n) { rowptr[base + 1] = p1; cnt[base + 1] = p1; }
    if (base + 2 < n) { rowptr[base + 2] = p2; cnt[base + 2] = p2; }
    if (base + 3 < n) { rowptr[base + 3] = p3; cnt[base + 3] = p3; }
    if (blockIdx.x == 0 && t == 0) rowptr[n] = ne;
}

__global__ void k_scatter(const int* __restrict__ row, const int* __restrict__ col,
                          const float* __restrict__ val, int ne,
                          int* __restrict__ cur, int2* __restrict__ ep) {
    int e = blockIdx.x * blockDim.x + threadIdx.x;
    if (e >= ne) return;
    int p = atomicAdd(&cur[row[e]], 1);
    ep[p] = make_int2(col[e], __float_as_int(val[e]));
}

// ---------------- warp-per-row gather SpMM ----------------
// lane owns float2 (dims lane*2, lane*2+1); warp reads contiguous 256B per edge.

__device__ __forceinline__ float2 f2fma(float2 a, float v, float2 x) {
    a.x += v * x.x; a.y += v * x.y; return a;
}

// layer 1: x gathered from concat(user,item)
__global__ void k_adj1(const int2* __restrict__ ep, const int* __restrict__ rp,
                       const float* __restrict__ user, const float* __restrict__ item,
                       float* __restrict__ out) {
    int r = blockIdx.x * 8 + (threadIdx.x >> 5);
    if (r >= NN) return;
    int lane = threadIdx.x & 31;
    int s = rp[r], e = rp[r + 1];
    float2 acc = make_float2(0.f, 0.f);
    int p = s;
    for (; p + 2 <= e; p += 2) {
        int2 cv0 = ep[p], cv1 = ep[p + 1];
        const float2* x0 = (const float2*)(cv0.x < NUM_USERS ? user + (size_t)cv0.x * EMB
                                                             : item + (size_t)(cv0.x - NUM_USERS) * EMB);
        const float2* x1 = (const float2*)(cv1.x < NUM_USERS ? user + (size_t)cv1.x * EMB
                                                             : item + (size_t)(cv1.x - NUM_USERS) * EMB);
        float2 a = x0[lane], b = x1[lane];
        acc = f2fma(acc, __int_as_float(cv0.y), a);
        acc = f2fma(acc, __int_as_float(cv1.y), b);
    }
    if (p < e) {
        int2 cv = ep[p];
        const float2* x0 = (const float2*)(cv.x < NUM_USERS ? user + (size_t)cv.x * EMB
                                                            : item + (size_t)(cv.x - NUM_USERS) * EMB);
        acc = f2fma(acc, __int_as_float(cv.y), x0[lane]);
    }
    ((float2*)(out + (size_t)r * EMB))[lane] = acc;
}

// layer 2: plain x -> out
__global__ void k_adj2(const int2* __restrict__ ep, const int* __restrict__ rp,
                       const float* __restrict__ x, float* __restrict__ out) {
    int r = blockIdx.x * 8 + (threadIdx.x >> 5);
    if (r >= NN) return;
    int lane = threadIdx.x & 31;
    int s = rp[r], e = rp[r + 1];
    float2 acc = make_float2(0.f, 0.f);
    int p = s;
    for (; p + 2 <= e; p += 2) {
        int2 cv0 = ep[p], cv1 = ep[p + 1];
        float2 a = ((const float2*)(x + (size_t)cv0.x * EMB))[lane];
        float2 b = ((const float2*)(x + (size_t)cv1.x * EMB))[lane];
        acc = f2fma(acc, __int_as_float(cv0.y), a);
        acc = f2fma(acc, __int_as_float(cv1.y), b);
    }
    if (p < e) {
        int2 cv = ep[p];
        acc = f2fma(acc, __int_as_float(cv.y),
                    ((const float2*)(x + (size_t)cv.x * EMB))[lane]);
    }
    ((float2*)(out + (size_t)r * EMB))[lane] = acc;
}

// layer 3 + final combine: out = 0.25*(e0 + ea + eb + A*eb)
__global__ void k_adj3(const int2* __restrict__ ep, const int* __restrict__ rp,
                       const float* __restrict__ user, const float* __restrict__ item,
                       const float* __restrict__ ea, const float* __restrict__ eb,
                       float* __restrict__ out) {
    int r = blockIdx.x * 8 + (threadIdx.x >> 5);
    if (r >= NN) return;
    int lane = threadIdx.x & 31;
    int s = rp[r], e = rp[r + 1];
    float2 acc = make_float2(0.f, 0.f);
    int p = s;
    for (; p + 2 <= e; p += 2) {
        int2 cv0 = ep[p], cv1 = ep[p + 1];
        float2 a = ((const float2*)(eb + (size_t)cv0.x * EMB))[lane];
        float2 b = ((const float2*)(eb + (size_t)cv1.x * EMB))[lane];
        acc = f2fma(acc, __int_as_float(cv0.y), a);
        acc = f2fma(acc, __int_as_float(cv1.y), b);
    }
    if (p < e) {
        int2 cv = ep[p];
        acc = f2fma(acc, __int_as_float(cv.y),
                    ((const float2*)(eb + (size_t)cv.x * EMB))[lane]);
    }
    const float2* base = (const float2*)(r < NUM_USERS ? user + (size_t)r * EMB
                                                       : item + (size_t)(r - NUM_USERS) * EMB);
    float2 b0 = base[lane];
    float2 a1 = ((const float2*)(ea + (size_t)r * EMB))[lane];
    float2 a2 = ((const float2*)(eb + (size_t)r * EMB))[lane];
    float2 o;
    o.x = 0.25f * (b0.x + a1.x + a2.x + acc.x);
    o.y = 0.25f * (b0.y + a1.y + a2.y + acc.y);
    ((float2*)(out + (size_t)r * EMB))[lane] = o;
}

// hv: bic[r] = (Hv * item)[r] / deg(r)
__global__ void k_hv(const int2* __restrict__ ep, const int* __restrict__ rp,
                     const float* __restrict__ item, float* __restrict__ bic) {
    int r = blockIdx.x * 8 + (threadIdx.x >> 5);
    if (r >= NBIC) return;
    int lane = threadIdx.x & 31;
    int s = rp[r], e = rp[r + 1];
    float2 acc = make_float2(0.f, 0.f);
    float deg = 0.f;
    for (int p = s; p < e; p++) {
        int2 cv = ep[p];
        float v = __int_as_float(cv.y);
        deg += v;
        acc = f2fma(acc, v, ((const float2*)(item + (size_t)cv.x * EMB))[lane]);
    }
    float inv = (deg == 0.f) ? 1.f : (1.f / deg);
    acc.x *= inv; acc.y *= inv;
    ((float2*)(bic + (size_t)r * EMB))[lane] = acc;
}

// hu: out[user r] += (Hu * bic)[r] / deg(r)
__global__ void k_hu(const int2* __restrict__ ep, const int* __restrict__ rp,
                     const float* __restrict__ bic, float* __restrict__ out) {
    int r = blockIdx.x * 8 + (threadIdx.x >> 5);
    if (r >= NUM_USERS) return;
    int lane = threadIdx.x & 31;
    int s = rp[r], e = rp[r + 1];
    float2 acc = make_float2(0.f, 0.f);
    float deg = 0.f;
    for (int p = s; p < e; p++) {
        int2 cv = ep[p];
        float v = __int_as_float(cv.y);
        deg += v;
        acc = f2fma(acc, v, ((const float2*)(bic + (size_t)cv.x * EMB))[lane]);
    }
    float inv = (deg == 0.f) ? 1.f : (1.f / deg);
    float2* op = (float2*)(out + (size_t)r * EMB);
    float2 o = op[lane];
    o.x += acc.x * inv;
    o.y += acc.y * inv;
    op[lane] = o;
}

// ---------------- launch ----------------
extern "C" void kernel_launch(void* const* d_in, const int* in_sizes, int n_in,
                              void* d_out, int out_size) {
    const float* user    = (const float*)d_in[0];
    const float* item    = (const float*)d_in[1];
    const float* adj_val = (const float*)d_in[2];
    const float* hv_val  = (const float*)d_in[3];
    const float* hu_val  = (const float*)d_in[4];
    const int*   adj_row = (const int*)d_in[5];
    const int*   adj_col = (const int*)d_in[6];
    const int*   hv_row  = (const int*)d_in[7];
    const int*   hv_col  = (const int*)d_in[8];
    const int*   hu_row  = (const int*)d_in[9];
    const int*   hu_col  = (const int*)d_in[10];
    float* out = (float*)d_out;

    const int E_adj = in_sizes[2];
    const int E_hv  = in_sizes[3];
    const int E_hu  = in_sizes[4];

    float *ea, *eb, *bic;
    int *cnt_adj, *rp_adj, *cnt_hv, *rp_hv, *cnt_hu, *rp_hu, *bsum;
    int2 *ep_adj, *ep_hv, *ep_hu;
    cudaGetSymbolAddress((void**)&ea, g_ea);
    cudaGetSymbolAddress((void**)&eb, g_eb);
    cudaGetSymbolAddress((void**)&bic, g_bic);
    cudaGetSymbolAddress((void**)&cnt_adj, g_cnt_adj);
    cudaGetSymbolAddress((void**)&rp_adj, g_rp_adj);
    cudaGetSymbolAddress((void**)&ep_adj, g_ep_adj);
    cudaGetSymbolAddress((void**)&cnt_hv, g_cnt_hv);
    cudaGetSymbolAddress((void**)&rp_hv, g_rp_hv);
    cudaGetSymbolAddress((void**)&ep_hv, g_ep_hv);
    cudaGetSymbolAddress((void**)&cnt_hu, g_cnt_hu);
    cudaGetSymbolAddress((void**)&rp_hu, g_rp_hu);
    cudaGetSymbolAddress((void**)&ep_hu, g_ep_hu);
    cudaGetSymbolAddress((void**)&bsum, g_bsum);

    const int TB = 256;
    auto nb = [](int n) { return (n + 1023) / 1024; };   // blocks for scan (1024 elems/blk)

    // ---- CSR builds ----
    k_zero_cnt<<<(NN + TB - 1) / TB, TB>>>();
    k_hist<<<(E_adj + TB - 1) / TB, TB>>>(adj_row, E_adj, cnt_adj);
    k_hist<<<(E_hv  + TB - 1) / TB, TB>>>(hv_row,  E_hv,  cnt_hv);
    k_hist<<<(E_hu  + TB - 1) / TB, TB>>>(hu_row,  E_hu,  cnt_hu);

    // adj scan
    k_blocksum<<<nb(NN), TB>>>(cnt_adj, NN, bsum);
    k_scan_bsum<<<1, TB>>>(bsum, nb(NN));
    k_scan_chunk<<<nb(NN), TB>>>(cnt_adj, NN, E_adj, bsum, rp_adj);
    k_scatter<<<(E_adj + TB - 1) / TB, TB>>>(adj_row, adj_col, adj_val, E_adj, cnt_adj, ep_adj);

    // hv scan
    k_blocksum<<<nb(NBIC), TB>>>(cnt_hv, NBIC, bsum);
    k_scan_bsum<<<1, TB>>>(bsum, nb(NBIC));
    k_scan_chunk<<<nb(NBIC), TB>>>(cnt_hv, NBIC, E_hv, bsum, rp_hv);
    k_scatter<<<(E_hv + TB - 1) / TB, TB>>>(hv_row, hv_col, hv_val, E_hv, cnt_hv, ep_hv);

    // hu scan
    k_blocksum<<<nb(NUM_USERS), TB>>>(cnt_hu, NUM_USERS, bsum);
    k_scan_bsum<<<1, TB>>>(bsum, nb(NUM_USERS));
    k_scan_chunk<<<nb(NUM_USERS), TB>>>(cnt_hu, NUM_USERS, E_hu, bsum, rp_hu);
    k_scatter<<<(E_hu + TB - 1) / TB, TB>>>(hu_row, hu_col, hu_val, E_hu, cnt_hu, ep_hu);

    // ---- SpMM chain (warp per row, 8 rows/block) ----
    k_adj1<<<(NN + 7) / 8, TB>>>(ep_adj, rp_adj, user, item, ea);
    k_adj2<<<(NN + 7) / 8, TB>>>(ep_adj, rp_adj, ea, eb);
    k_adj3<<<(NN + 7) / 8, TB>>>(ep_adj, rp_adj, user, item, ea, eb, out);

    k_hv<<<(NBIC + 7) / 8, TB>>>(ep_hv, rp_hv, item, bic);
    k_hu<<<(NUM_USERS + 7) / 8, TB>>>(ep_hu, rp_hu, bic, out);
}

// round 3
// speedup vs baseline: 2.7253x; 1.1466x over previous
#include <cuda_runtime.h>

#define NUM_USERS 100000
#define NUM_ITEMS 50000
#define NN        (NUM_USERS + NUM_ITEMS)   // 150000
#define EMB       64
#define NBIC      20000
#define E_ADJ_MAX 1200000
#define E_HV_MAX  400000
#define E_HU_MAX  400000

// counts laid out in one array: [adj(NN) | hv(NBIC) | hu(NUM_USERS)]
#define CNT_ADJ_OFF 0
#define CNT_HV_OFF  (NN)
#define CNT_HU_OFF  (NN + NBIC)
#define CNT_TOT     (NN + NBIC + NUM_USERS)      // 270000

// rowptrs in one array
#define RP_ADJ_OFF 0
#define RP_HV_OFF  (NN + 1)
#define RP_HU_OFF  (NN + 1 + NBIC + 1)
#define RP_TOT     (NN + NBIC + NUM_USERS + 3)

// scan block counts (1024 elems per block)
#define NB_ADJ 147     // ceil(150000/1024)
#define NB_HV  20      // ceil(20000/1024)
#define NB_HU  98      // ceil(100000/1024)
#define NB_TOT (NB_ADJ + NB_HV + NB_HU)          // 265

// ---------------- static device scratch ----------------
__device__ __align__(16) float g_ea[NN * EMB];
__device__ __align__(16) float g_eb[NN * EMB];
__device__ __align__(16) float g_bic[NBIC * EMB];

__device__ int  g_cnt[CNT_TOT];      // histogram -> scatter cursor
__device__ int  g_rp[RP_TOT];        // rowptrs
__device__ int  g_bsum[NB_TOT];

__device__ int2 g_ep_adj[E_ADJ_MAX]; // packed (col, val-bits)
__device__ int2 g_ep_hv[E_HV_MAX];
__device__ int2 g_ep_hu[E_HU_MAX];

// ---------------- CSR build (fused) ----------------

__global__ void k_zero_cnt() {
    int i = blockIdx.x * blockDim.x + threadIdx.x;
    if (i < CNT_TOT) g_cnt[i] = 0;
}

__global__ void k_hist_all(const int* __restrict__ adj_row,
                           const int* __restrict__ hv_row,
                           const int* __restrict__ hu_row,
                           int e_adj, int e_hv, int e_hu) {
    int i = blockIdx.x * blockDim.x + threadIdx.x;
    if (i < e_adj) {
        atomicAdd(&g_cnt[CNT_ADJ_OFF + adj_row[i]], 1);
    } else if (i < e_adj + e_hv) {
        atomicAdd(&g_cnt[CNT_HV_OFF + hv_row[i - e_adj]], 1);
    } else if (i < e_adj + e_hv + e_hu) {
        atomicAdd(&g_cnt[CNT_HU_OFF + hu_row[i - e_adj - e_hv]], 1);
    }
}

__device__ __forceinline__ void seg_map(int b, int& cnt_off, int& n, int& local) {
    if (b < NB_ADJ)              { cnt_off = CNT_ADJ_OFF; n = NN;        local = b; }
    else if (b < NB_ADJ + NB_HV) { cnt_off = CNT_HV_OFF;  n = NBIC;      local = b - NB_ADJ; }
    else                         { cnt_off = CNT_HU_OFF;  n = NUM_USERS; local = b - NB_ADJ - NB_HV; }
}

__global__ void k_blocksum_all() {
    __shared__ int sm[256];
    int cnt_off, n, local;
    seg_map(blockIdx.x, cnt_off, n, local);
    int t = threadIdx.x;
    int base = local * 1024 + t * 4;
    int s = 0;
    #pragma unroll
    for (int i = 0; i < 4; i++) { int idx = base + i; if (idx < n) s += g_cnt[cnt_off + idx]; }
    sm[t] = s; __syncthreads();
    for (int o = 128; o > 0; o >>= 1) {
        if (t < o) sm[t] += sm[t + o];
        __syncthreads();
    }
    if (t == 0) g_bsum[blockIdx.x] = sm[0];
}

// 3 warps, warp w scans its segment of bsum (exclusive), chunked shfl scan
__global__ void k_scan_bsum_all() {
    int w = threadIdx.x >> 5;
    int lane = threadIdx.x & 31;
    if (w >= 3) return;
    int base = (w == 0) ? 0 : (w == 1) ? NB_ADJ : (NB_ADJ + NB_HV);
    int len  = (w == 0) ? NB_ADJ : (w == 1) ? NB_HV : NB_HU;
    int carry = 0;
    for (int start = 0; start < len; start += 32) {
        int idx = start + lane;
        int v = (idx < len) ? g_bsum[base + idx] : 0;
        int x = v;
        #pragma unroll
        for (int o = 1; o < 32; o <<= 1) {
            int tt = __shfl_up_sync(0xffffffffu, x, o);
            if (lane >= o) x += tt;
        }
        if (idx < len) g_bsum[base + idx] = x - v + carry;
        carry += __shfl_sync(0xffffffffu, x, 31);
    }
}

__global__ void k_scan_chunk_all(int e_adj, int e_hv, int e_hu) {
    __shared__ int sm[256];
    int b = blockIdx.x;
    int cnt_off, n, local;
    seg_map(b, cnt_off, n, local);
    int rp_off, ne;
    if (b < NB_ADJ)              { rp_off = RP_ADJ_OFF; ne = e_adj; }
    else if (b < NB_ADJ + NB_HV) { rp_off = RP_HV_OFF;  ne = e_hv; }
    else                         { rp_off = RP_HU_OFF;  ne = e_hu; }

    int t = threadIdx.x;
    int base = local * 1024 + t * 4;
    int c0 = 0, c1 = 0, c2 = 0, c3 = 0;
    if (base + 0 < n) c0 = g_cnt[cnt_off + base + 0];
    if (base + 1 < n) c1 = g_cnt[cnt_off + base + 1];
    if (base + 2 < n) c2 = g_cnt[cnt_off + base + 2];
    if (base + 3 < n) c3 = g_cnt[cnt_off + base + 3];
    int tot = c0 + c1 + c2 + c3;
    sm[t] = tot; __syncthreads();
    for (int o = 1; o < 256; o <<= 1) {
        int x = (t >= o) ? sm[t - o] : 0;
        __syncthreads();
        sm[t] += x;
        __syncthreads();
    }
    int pre = sm[t] - tot + g_bsum[b];
    int p0 = pre, p1 = pre + c0, p2 = p1 + c1, p3 = p2 + c2;
    if (base + 0 < n) { g_rp[rp_off + base + 0] = p0; g_cnt[cnt_off + base + 0] = p0; }
    if (base + 1 < n) { g_rp[rp_off + base + 1] = p1; g_cnt[cnt_off + base + 1] = p1; }
    if (base + 2 < n) { g_rp[rp_off + base + 2] = p2; g_cnt[cnt_off + base + 2] = p2; }
    if (base + 3 < n) { g_rp[rp_off + base + 3] = p3; g_cnt[cnt_off + base + 3] = p3; }
    if (local == 0 && t == 0) g_rp[rp_off + n] = ne;
}

__global__ void k_scatter_all(const int* __restrict__ adj_row, const int* __restrict__ adj_col,
                              const float* __restrict__ adj_val,
                              const int* __restrict__ hv_row, const int* __restrict__ hv_col,
                              const float* __restrict__ hv_val,
                              const int* __restrict__ hu_row, const int* __restrict__ hu_col,
                              const float* __restrict__ hu_val,
                              int e_adj, int e_hv, int e_hu) {
    int i = blockIdx.x * blockDim.x + threadIdx.x;
    if (i < e_adj) {
        int p = atomicAdd(&g_cnt[CNT_ADJ_OFF + adj_row[i]], 1);
        g_ep_adj[p] = make_int2(adj_col[i], __float_as_int(adj_val[i]));
    } else if (i < e_adj + e_hv) {
        int j = i - e_adj;
        int p = atomicAdd(&g_cnt[CNT_HV_OFF + hv_row[j]], 1);
        g_ep_hv[p] = make_int2(hv_col[j], __float_as_int(hv_val[j]));
    } else if (i < e_adj + e_hv + e_hu) {
        int j = i - e_adj - e_hv;
        int p = atomicAdd(&g_cnt[CNT_HU_OFF + hu_row[j]], 1);
        g_ep_hu[p] = make_int2(hu_col[j], __float_as_int(hu_val[j]));
    }
}

// ---------------- half-warp float4 gather SpMM ----------------
// warp owns a row; half-warps (16 lanes, float4 each = 256B/edge) process
// interleaved edges, unrolled x2 -> 4 outstanding gathers per warp.

__device__ __forceinline__ void f4fma(float4& a, float v, float4 x) {
    a.x += v * x.x; a.y += v * x.y; a.z += v * x.z; a.w += v * x.w;
}

__device__ __forceinline__ void f4comb(float4& a) {   // add partner half-warp's acc
    a.x += __shfl_xor_sync(0xffffffffu, a.x, 16);
    a.y += __shfl_xor_sync(0xffffffffu, a.y, 16);
    a.z += __shfl_xor_sync(0xffffffffu, a.z, 16);
    a.w += __shfl_xor_sync(0xffffffffu, a.w, 16);
}

// layer 1: x gathered from concat(user,item)
__global__ void k_adj1(const float* __restrict__ user, const float* __restrict__ item,
                       float* __restrict__ out) {
    int r = blockIdx.x * 8 + (threadIdx.x >> 5);
    if (r >= NN) return;
    int lane = threadIdx.x & 31;
    int h = lane >> 4, l16 = lane & 15;
    int s = g_rp[RP_ADJ_OFF + r], e = g_rp[RP_ADJ_OFF + r + 1];
    float4 acc = make_float4(0.f, 0.f, 0.f, 0.f);
    int p = s + h;
    for (; p + 2 < e; p += 4) {
        int2 cv0 = g_ep_adj[p], cv1 = g_ep_adj[p + 2];
        const float4* x0 = (const float4*)(cv0.x < NUM_USERS ? user + (size_t)cv0.x * EMB
                                                             : item + (size_t)(cv0.x - NUM_USERS) * EMB);
        const float4* x1 = (const float4*)(cv1.x < NUM_USERS ? user + (size_t)cv1.x * EMB
                                                             : item + (size_t)(cv1.x - NUM_USERS) * EMB);
        float4 a = x0[l16], b = x1[l16];
        f4fma(acc, __int_as_float(cv0.y), a);
        f4fma(acc, __int_as_float(cv1.y), b);
    }
    if (p < e) {
        int2 cv = g_ep_adj[p];
        const float4* x0 = (const float4*)(cv.x < NUM_USERS ? user + (size_t)cv.x * EMB
                                                            : item + (size_t)(cv.x - NUM_USERS) * EMB);
        f4fma(acc, __int_as_float(cv.y), x0[l16]);
    }
    f4comb(acc);
    if (h == 0) ((float4*)(out + (size_t)r * EMB))[l16] = acc;
}

// layer 2: plain x -> out
__global__ void k_adj2(const float* __restrict__ x, float* __restrict__ out) {
    int r = blockIdx.x * 8 + (threadIdx.x >> 5);
    if (r >= NN) return;
    int lane = threadIdx.x & 31;
    int h = lane >> 4, l16 = lane & 15;
    int s = g_rp[RP_ADJ_OFF + r], e = g_rp[RP_ADJ_OFF + r + 1];
    float4 acc = make_float4(0.f, 0.f, 0.f, 0.f);
    int p = s + h;
    for (; p + 2 < e; p += 4) {
        int2 cv0 = g_ep_adj[p], cv1 = g_ep_adj[p + 2];
        float4 a = ((const float4*)(x + (size_t)cv0.x * EMB))[l16];
        float4 b = ((const float4*)(x + (size_t)cv1.x * EMB))[l16];
        f4fma(acc, __int_as_float(cv0.y), a);
        f4fma(acc, __int_as_float(cv1.y), b);
    }
    if (p < e) {
        int2 cv = g_ep_adj[p];
        f4fma(acc, __int_as_float(cv.y), ((const float4*)(x + (size_t)cv.x * EMB))[l16]);
    }
    f4comb(acc);
    if (h == 0) ((float4*)(out + (size_t)r * EMB))[l16] = acc;
}

// layer 3 + combine: out = 0.25*(e0 + ea + eb + A*eb)
__global__ void k_adj3(const float* __restrict__ user, const float* __restrict__ item,
                       const float* __restrict__ ea, const float* __restrict__ eb,
                       float* __restrict__ out) {
    int r = blockIdx.x * 8 + (threadIdx.x >> 5);
    if (r >= NN) return;
    int lane = threadIdx.x & 31;
    int h = lane >> 4, l16 = lane & 15;
    int s = g_rp[RP_ADJ_OFF + r], e = g_rp[RP_ADJ_OFF + r + 1];
    float4 acc = make_float4(0.f, 0.f, 0.f, 0.f);
    int p = s + h;
    for (; p + 2 < e; p += 4) {
        int2 cv0 = g_ep_adj[p], cv1 = g_ep_adj[p + 2];
        float4 a = ((const float4*)(eb + (size_t)cv0.x * EMB))[l16];
        float4 b = ((const float4*)(eb + (size_t)cv1.x * EMB))[l16];
        f4fma(acc, __int_as_float(cv0.y), a);
        f4fma(acc, __int_as_float(cv1.y), b);
    }
    if (p < e) {
        int2 cv = g_ep_adj[p];
        f4fma(acc, __int_as_float(cv.y), ((const float4*)(eb + (size_t)cv.x * EMB))[l16]);
    }
    f4comb(acc);
    if (h == 0) {
        const float4* base = (const float4*)(r < NUM_USERS ? user + (size_t)r * EMB
                                                           : item + (size_t)(r - NUM_USERS) * EMB);
        float4 b0 = base[l16];
        float4 a1 = ((const float4*)(ea + (size_t)r * EMB))[l16];
        float4 a2 = ((const float4*)(eb + (size_t)r * EMB))[l16];
        float4 o;
        o.x = 0.25f * (b0.x + a1.x + a2.x + acc.x);
        o.y = 0.25f * (b0.y + a1.y + a2.y + acc.y);
        o.z = 0.25f * (b0.z + a1.z + a2.z + acc.z);
        o.w = 0.25f * (b0.w + a1.w + a2.w + acc.w);
        ((float4*)(out + (size_t)r * EMB))[l16] = o;
    }
}

// hv: bic[r] = (Hv * item)[r] / deg(r)
__global__ void k_hv(const float* __restrict__ item, float* __restrict__ bic) {
    int r = blockIdx.x * 8 + (threadIdx.x >> 5);
    if (r >= NBIC) return;
    int lane = threadIdx.x & 31;
    int h = lane >> 4, l16 = lane & 15;
    int s = g_rp[RP_HV_OFF + r], e = g_rp[RP_HV_OFF + r + 1];
    float4 acc = make_float4(0.f, 0.f, 0.f, 0.f);
    float deg = 0.f;
    int p = s + h;
    for (; p + 2 < e; p += 4) {
        int2 cv0 = g_ep_hv[p], cv1 = g_ep_hv[p + 2];
        float v0 = __int_as_float(cv0.y), v1 = __int_as_float(cv1.y);
        float4 a = ((const float4*)(item + (size_t)cv0.x * EMB))[l16];
        float4 b = ((const float4*)(item + (size_t)cv1.x * EMB))[l16];
        deg += v0 + v1;
        f4fma(acc, v0, a);
        f4fma(acc, v1, b);
    }
    if (p < e) {
        int2 cv = g_ep_hv[p];
        float v = __int_as_float(cv.y);
        deg += v;
        f4fma(acc, v, ((const float4*)(item + (size_t)cv.x * EMB))[l16]);
    }
    f4comb(acc);
    deg += __shfl_xor_sync(0xffffffffu, deg, 16);
    if (h == 0) {
        float inv = (deg == 0.f) ? 1.f : (1.f / deg);
        acc.x *= inv; acc.y *= inv; acc.z *= inv; acc.w *= inv;
        ((float4*)(bic + (size_t)r * EMB))[l16] = acc;
    }
}

// hu: out[user r] += (Hu * bic)[r] / deg(r)
__global__ void k_hu(const float* __restrict__ bic, float* __restrict__ out) {
    int r = blockIdx.x * 8 + (threadIdx.x >> 5);
    if (r >= NUM_USERS) return;
    int lane = threadIdx.x & 31;
    int h = lane >> 4, l16 = lane & 15;
    int s = g_rp[RP_HU_OFF + r], e = g_rp[RP_HU_OFF + r + 1];
    float4 acc = make_float4(0.f, 0.f, 0.f, 0.f);
    float deg = 0.f;
    int p = s + h;
    for (; p + 2 < e; p += 4) {
        int2 cv0 = g_ep_hu[p], cv1 = g_ep_hu[p + 2];
        float v0 = __int_as_float(cv0.y), v1 = __int_as_float(cv1.y);
        float4 a = ((const float4*)(bic + (size_t)cv0.x * EMB))[l16];
        float4 b = ((const float4*)(bic + (size_t)cv1.x * EMB))[l16];
        deg += v0 + v1;
        f4fma(acc, v0, a);
        f4fma(acc, v1, b);
    }
    if (p < e) {
        int2 cv = g_ep_hu[p];
        float v = __int_as_float(cv.y);
        deg += v;
        f4fma(acc, v, ((const float4*)(bic + (size_t)cv.x * EMB))[l16]);
    }
    f4comb(acc);
    deg += __shfl_xor_sync(0xffffffffu, deg, 16);
    if (h == 0) {
        float inv = (deg == 0.f) ? 1.f : (1.f / deg);
        float4* op = (float4*)(out + (size_t)r * EMB);
        float4 o = op[l16];
        o.x += acc.x * inv; o.y += acc.y * inv;
        o.z += acc.z * inv; o.w += acc.w * inv;
        op[l16] = o;
    }
}

// ---------------- launch ----------------
extern "C" void kernel_launch(void* const* d_in, const int* in_sizes, int n_in,
                              void* d_out, int out_size) {
    const float* user    = (const float*)d_in[0];
    const float* item    = (const float*)d_in[1];
    const float* adj_val = (const float*)d_in[2];
    const float* hv_val  = (const float*)d_in[3];
    const float* hu_val  = (const float*)d_in[4];
    const int*   adj_row = (const int*)d_in[5];
    const int*   adj_col = (const int*)d_in[6];
    const int*   hv_row  = (const int*)d_in[7];
    const int*   hv_col  = (const int*)d_in[8];
    const int*   hu_row  = (const int*)d_in[9];
    const int*   hu_col  = (const int*)d_in[10];
    float* out = (float*)d_out;

    const int E_adj = in_sizes[2];
    const int E_hv  = in_sizes[3];
    const int E_hu  = in_sizes[4];

    float *ea, *eb, *bic;
    cudaGetSymbolAddress((void**)&ea,  g_ea);
    cudaGetSymbolAddress((void**)&eb,  g_eb);
    cudaGetSymbolAddress((void**)&bic, g_bic);

    const int TB = 256;
    const int ne_tot = E_adj + E_hv + E_hu;

    // ---- CSR build: 6 launches ----
    k_zero_cnt<<<(CNT_TOT + TB - 1) / TB, TB>>>();
    k_hist_all<<<(ne_tot + TB - 1) / TB, TB>>>(adj_row, hv_row, hu_row, E_adj, E_hv, E_hu);
    k_blocksum_all<<<NB_TOT, TB>>>();
    k_scan_bsum_all<<<1, 96>>>();
    k_scan_chunk_all<<<NB_TOT, TB>>>(E_adj, E_hv, E_hu);
    k_scatter_all<<<(ne_tot + TB - 1) / TB, TB>>>(adj_row, adj_col, adj_val,
                                                  hv_row, hv_col, hv_val,
                                                  hu_row, hu_col, hu_val,
                                                  E_adj, E_hv, E_hu);

    // ---- SpMM chain: 5 launches ----
    k_adj1<<<(NN + 7) / 8, TB>>>(user, item, ea);
    k_hv<<<(NBIC + 7) / 8, TB>>>(item, bic);
    k_adj2<<<(NN + 7) / 8, TB>>>(ea, eb);
    k_adj3<<<(NN + 7) / 8, TB>>>(user, item, ea, eb, out);
    k_hu<<<(NUM_USERS + 7) / 8, TB>>>(bic, out);
}

// round 4
// speedup vs baseline: 2.7364x; 1.0041x over previous
#include <cuda_runtime.h>

#define NUM_USERS 100000
#define NUM_ITEMS 50000
#define NN        (NUM_USERS + NUM_ITEMS)   // 150000
#define EMB       64
#define NBIC      20000
#define E_ADJ_MAX 1200000
#define E_HV_MAX  400000
#define E_HU_MAX  400000

// counts laid out in one array: [adj(NN) | hv(NBIC) | hu(NUM_USERS)]
#define CNT_ADJ_OFF 0
#define CNT_HV_OFF  (NN)
#define CNT_HU_OFF  (NN + NBIC)
#define CNT_TOT     (NN + NBIC + NUM_USERS)      // 270000

// rowptrs in one array
#define RP_ADJ_OFF 0
#define RP_HV_OFF  (NN + 1)
#define RP_HU_OFF  (NN + 1 + NBIC + 1)
#define RP_TOT     (NN + NBIC + NUM_USERS + 3)

// scan block counts (1024 elems per block)
#define NB_ADJ 147     // ceil(150000/1024)
#define NB_HV  20      // ceil(20000/1024)
#define NB_HU  98      // ceil(100000/1024)
#define NB_TOT (NB_ADJ + NB_HV + NB_HU)          // 265

// ---------------- static device scratch ----------------
__device__ __align__(16) float g_ea[NN * EMB];
__device__ __align__(16) float g_eb[NN * EMB];
__device__ __align__(16) float g_bic[NBIC * EMB];
__device__ __align__(16) float g_ul[NUM_USERS * EMB];

__device__ int  g_cnt[CNT_TOT];      // histogram -> scatter cursor
__device__ int  g_rp[RP_TOT];        // rowptrs
__device__ int  g_bsum[NB_TOT];

__device__ int2 g_ep_adj[E_ADJ_MAX]; // packed (col, val-bits)
__device__ int2 g_ep_hv[E_HV_MAX];
__device__ int2 g_ep_hu[E_HU_MAX];

// ---------------- CSR build ----------------

__global__ void k_zero_cnt() {
    int i = blockIdx.x * blockDim.x + threadIdx.x;
    if (i < CNT_TOT) g_cnt[i] = 0;
}

__global__ void k_hist_all(const int* __restrict__ adj_row,
                           const int* __restrict__ hv_row,
                           const int* __restrict__ hu_row,
                           int e_adj, int e_hv, int e_hu) {
    int i = blockIdx.x * blockDim.x + threadIdx.x;
    if (i < e_adj) {
        atomicAdd(&g_cnt[CNT_ADJ_OFF + adj_row[i]], 1);
    } else if (i < e_adj + e_hv) {
        atomicAdd(&g_cnt[CNT_HV_OFF + hv_row[i - e_adj]], 1);
    } else if (i < e_adj + e_hv + e_hu) {
        atomicAdd(&g_cnt[CNT_HU_OFF + hu_row[i - e_adj - e_hv]], 1);
    }
}

__device__ __forceinline__ void seg_map(int b, int& cnt_off, int& n, int& local,
                                        int& seg_b0, int& rp_off) {
    if (b < NB_ADJ) {
        cnt_off = CNT_ADJ_OFF; n = NN;        local = b;                  seg_b0 = 0;               rp_off = RP_ADJ_OFF;
    } else if (b < NB_ADJ + NB_HV) {
        cnt_off = CNT_HV_OFF;  n = NBIC;      local = b - NB_ADJ;         seg_b0 = NB_ADJ;          rp_off = RP_HV_OFF;
    } else {
        cnt_off = CNT_HU_OFF;  n = NUM_USERS; local = b - NB_ADJ - NB_HV; seg_b0 = NB_ADJ + NB_HV;  rp_off = RP_HU_OFF;
    }
}

__global__ void k_blocksum_all() {
    __shared__ int sm[256];
    int cnt_off, n, local, seg_b0, rp_off;
    seg_map(blockIdx.x, cnt_off, n, local, seg_b0, rp_off);
    int t = threadIdx.x;
    int base = local * 1024 + t * 4;
    int s = 0;
    #pragma unroll
    for (int i = 0; i < 4; i++) { int idx = base + i; if (idx < n) s += g_cnt[cnt_off + idx]; }
    sm[t] = s; __syncthreads();
    for (int o = 128; o > 0; o >>= 1) {
        if (t < o) sm[t] += sm[t + o];
        __syncthreads();
    }
    if (t == 0) g_bsum[blockIdx.x] = sm[0];
}

// per-chunk scan; block prefix computed inline from g_bsum (<=147 preds/segment)
__global__ void k_scan_chunk_all(int e_adj, int e_hv, int e_hu) {
    __shared__ int sm[256];
    int b = blockIdx.x;
    int cnt_off, n, local, seg_b0, rp_off;
    seg_map(b, cnt_off, n, local, seg_b0, rp_off);
    int ne = (b < NB_ADJ) ? e_adj : (b < NB_ADJ + NB_HV) ? e_hv : e_hu;

    int t = threadIdx.x;

    // inline prefix over predecessor block sums
    int pv = (t < local) ? g_bsum[seg_b0 + t] : 0;
    sm[t] = pv; __syncthreads();
    for (int o = 128; o > 0; o >>= 1) {
        if (t < o) sm[t] += sm[t + o];
        __syncthreads();
    }
    int blk_prefix = sm[0];
    __syncthreads();

    int base = local * 1024 + t * 4;
    int c0 = 0, c1 = 0, c2 = 0, c3 = 0;
    if (base + 0 < n) c0 = g_cnt[cnt_off + base + 0];
    if (base + 1 < n) c1 = g_cnt[cnt_off + base + 1];
    if (base + 2 < n) c2 = g_cnt[cnt_off + base + 2];
    if (base + 3 < n) c3 = g_cnt[cnt_off + base + 3];
    int tot = c0 + c1 + c2 + c3;
    sm[t] = tot; __syncthreads();
    for (int o = 1; o < 256; o <<= 1) {
        int x = (t >= o) ? sm[t - o] : 0;
        __syncthreads();
        sm[t] += x;
        __syncthreads();
    }
    int pre = sm[t] - tot + blk_prefix;
    int p0 = pre, p1 = pre + c0, p2 = p1 + c1, p3 = p2 + c2;
    if (base + 0 < n) { g_rp[rp_off + base + 0] = p0; g_cnt[cnt_off + base + 0] = p0; }
    if (base + 1 < n) { g_rp[rp_off + base + 1] = p1; g_cnt[cnt_off + base + 1] = p1; }
    if (base + 2 < n) { g_rp[rp_off + base + 2] = p2; g_cnt[cnt_off + base + 2] = p2; }
    if (base + 3 < n) { g_rp[rp_off + base + 3] = p3; g_cnt[cnt_off + base + 3] = p3; }
    if (local == 0 && t == 0) g_rp[rp_off + n] = ne;
}

__global__ void k_scatter_all(const int* __restrict__ adj_row, const int* __restrict__ adj_col,
                              const float* __restrict__ adj_val,
                              const int* __restrict__ hv_row, const int* __restrict__ hv_col,
                              const float* __restrict__ hv_val,
                              const int* __restrict__ hu_row, const int* __restrict__ hu_col,
                              const float* __restrict__ hu_val,
                              int e_adj, int e_hv, int e_hu) {
    int i = blockIdx.x * blockDim.x + threadIdx.x;
    if (i < e_adj) {
        int p = atomicAdd(&g_cnt[CNT_ADJ_OFF + adj_row[i]], 1);
        g_ep_adj[p] = make_int2(adj_col[i], __float_as_int(adj_val[i]));
    } else if (i < e_adj + e_hv) {
        int j = i - e_adj;
        int p = atomicAdd(&g_cnt[CNT_HV_OFF + hv_row[j]], 1);
        g_ep_hv[p] = make_int2(hv_col[j], __float_as_int(hv_val[j]));
    } else if (i < e_adj + e_hv + e_hu) {
        int j = i - e_adj - e_hv;
        int p = atomicAdd(&g_cnt[CNT_HU_OFF + hu_row[j]], 1);
        g_ep_hu[p] = make_int2(hu_col[j], __float_as_int(hu_val[j]));
    }
}

// ---------------- half-warp float4 gather SpMM cores ----------------

__device__ __forceinline__ void f4fma(float4& a, float v, float4 x) {
    a.x += v * x.x; a.y += v * x.y; a.z += v * x.z; a.w += v * x.w;
}

__device__ __forceinline__ void f4comb(float4& a) {
    a.x += __shfl_xor_sync(0xffffffffu, a.x, 16);
    a.y += __shfl_xor_sync(0xffffffffu, a.y, 16);
    a.z += __shfl_xor_sync(0xffffffffu, a.z, 16);
    a.w += __shfl_xor_sync(0xffffffffu, a.w, 16);
}

// gather over plain matrix x
__device__ __forceinline__ float4 spmm_row(const int2* __restrict__ ep, int s, int e,
                                           const float* __restrict__ x,
                                           int h, int l16, float* deg_out) {
    float4 acc = make_float4(0.f, 0.f, 0.f, 0.f);
    float deg = 0.f;
    int p = s + h;
    for (; p + 2 < e; p += 4) {
        int2 cv0 = ep[p], cv1 = ep[p + 2];
        float v0 = __int_as_float(cv0.y), v1 = __int_as_float(cv1.y);
        float4 a = ((const float4*)(x + (size_t)cv0.x * EMB))[l16];
        float4 b = ((const float4*)(x + (size_t)cv1.x * EMB))[l16];
        deg += v0 + v1;
        f4fma(acc, v0, a);
        f4fma(acc, v1, b);
    }
    if (p < e) {
        int2 cv = ep[p];
        float v = __int_as_float(cv.y);
        deg += v;
        f4fma(acc, v, ((const float4*)(x + (size_t)cv.x * EMB))[l16]);
    }
    if (deg_out) *deg_out = deg;
    return acc;
}

// ---------------- phase 1: adj1 (rows [0,NN)) + hv (rows [NN, NN+NBIC)) ----------------
__global__ void k_phase1(const float* __restrict__ user, const float* __restrict__ item,
                         float* __restrict__ ea, float* __restrict__ bic) {
    int r = blockIdx.x * 8 + (threadIdx.x >> 5);
    int lane = threadIdx.x & 31;
    int h = lane >> 4, l16 = lane & 15;

    if (r < NN) {
        // adj layer 1: gather from concat(user,item)
        int s = g_rp[RP_ADJ_OFF + r], e = g_rp[RP_ADJ_OFF + r + 1];
        float4 acc = make_float4(0.f, 0.f, 0.f, 0.f);
        int p = s + h;
        for (; p + 2 < e; p += 4) {
            int2 cv0 = g_ep_adj[p], cv1 = g_ep_adj[p + 2];
            const float4* x0 = (const float4*)(cv0.x < NUM_USERS ? user + (size_t)cv0.x * EMB
                                                                 : item + (size_t)(cv0.x - NUM_USERS) * EMB);
            const float4* x1 = (const float4*)(cv1.x < NUM_USERS ? user + (size_t)cv1.x * EMB
                                                                 : item + (size_t)(cv1.x - NUM_USERS) * EMB);
            float4 a = x0[l16], b = x1[l16];
            f4fma(acc, __int_as_float(cv0.y), a);
            f4fma(acc, __int_as_float(cv1.y), b);
        }
        if (p < e) {
            int2 cv = g_ep_adj[p];
            const float4* x0 = (const float4*)(cv.x < NUM_USERS ? user + (size_t)cv.x * EMB
                                                                : item + (size_t)(cv.x - NUM_USERS) * EMB);
            f4fma(acc, __int_as_float(cv.y), x0[l16]);
        }
        f4comb(acc);
        if (h == 0) ((float4*)(ea + (size_t)r * EMB))[l16] = acc;
    } else if (r < NN + NBIC) {
        int rr = r - NN;
        int s = g_rp[RP_HV_OFF + rr], e = g_rp[RP_HV_OFF + rr + 1];
        float deg;
        float4 acc = spmm_row(g_ep_hv, s, e, item, h, l16, &deg);
        f4comb(acc);
        deg += __shfl_xor_sync(0xffffffffu, deg, 16);
        if (h == 0) {
            float inv = (deg == 0.f) ? 1.f : (1.f / deg);
            acc.x *= inv; acc.y *= inv; acc.z *= inv; acc.w *= inv;
            ((float4*)(bic + (size_t)rr * EMB))[l16] = acc;
        }
    }
}

// ---------------- phase 2: adj2 (rows [0,NN)) + hu (rows [NN, NN+NUM_USERS)) ----------------
__global__ void k_phase2(const float* __restrict__ ea, float* __restrict__ eb,
                         const float* __restrict__ bic, float* __restrict__ ul) {
    int r = blockIdx.x * 8 + (threadIdx.x >> 5);
    int lane = threadIdx.x & 31;
    int h = lane >> 4, l16 = lane & 15;

    if (r < NN) {
        int s = g_rp[RP_ADJ_OFF + r], e = g_rp[RP_ADJ_OFF + r + 1];
        float4 acc = spmm_row(g_ep_adj, s, e, ea, h, l16, nullptr);
        f4comb(acc);
        if (h == 0) ((float4*)(eb + (size_t)r * EMB))[l16] = acc;
    } else if (r < NN + NUM_USERS) {
        int rr = r - NN;
        int s = g_rp[RP_HU_OFF + rr], e = g_rp[RP_HU_OFF + rr + 1];
        float deg;
        float4 acc = spmm_row(g_ep_hu, s, e, bic, h, l16, &deg);
        f4comb(acc);
        deg += __shfl_xor_sync(0xffffffffu, deg, 16);
        if (h == 0) {
            float inv = (deg == 0.f) ? 1.f : (1.f / deg);
            acc.x *= inv; acc.y *= inv; acc.z *= inv; acc.w *= inv;
            ((float4*)(ul + (size_t)rr * EMB))[l16] = acc;
        }
    }
}

// ---------------- phase 3: adj3 + full epilogue ----------------
// out = 0.25*(e0 + ea + eb + A*eb) + (r < NUM_USERS ? ul[r] : 0)
__global__ void k_phase3(const float* __restrict__ user, const float* __restrict__ item,
                         const float* __restrict__ ea, const float* __restrict__ eb,
                         const float* __restrict__ ul, float* __restrict__ out) {
    int r = blockIdx.x * 8 + (threadIdx.x >> 5);
    if (r >= NN) return;
    int lane = threadIdx.x & 31;
    int h = lane >> 4, l16 = lane & 15;
    int s = g_rp[RP_ADJ_OFF + r], e = g_rp[RP_ADJ_OFF + r + 1];
    float4 acc = spmm_row(g_ep_adj, s, e, eb, h, l16, nullptr);
    f4comb(acc);
    if (h == 0) {
        const float4* base = (const float4*)(r < NUM_USERS ? user + (size_t)r * EMB
                                                           : item + (size_t)(r - NUM_USERS) * EMB);
        float4 b0 = base[l16];
        float4 a1 = ((const float4*)(ea + (size_t)r * EMB))[l16];
        float4 a2 = ((const float4*)(eb + (size_t)r * EMB))[l16];
        float4 o;
        o.x = 0.25f * (b0.x + a1.x + a2.x + acc.x);
        o.y = 0.25f * (b0.y + a1.y + a2.y + acc.y);
        o.z = 0.25f * (b0.z + a1.z + a2.z + acc.z);
        o.w = 0.25f * (b0.w + a1.w + a2.w + acc.w);
        if (r < NUM_USERS) {
            float4 l = ((const float4*)(ul + (size_t)r * EMB))[l16];
            o.x += l.x; o.y += l.y; o.z += l.z; o.w += l.w;
        }
        ((float4*)(out + (size_t)r * EMB))[l16] = o;
    }
}

// ---------------- launch ----------------
extern "C" void kernel_launch(void* const* d_in, const int* in_sizes, int n_in,
                              void* d_out, int out_size) {
    const float* user    = (const float*)d_in[0];
    const float* item    = (const float*)d_in[1];
    const float* adj_val = (const float*)d_in[2];
    const float* hv_val  = (const float*)d_in[3];
    const float* hu_val  = (const float*)d_in[4];
    const int*   adj_row = (const int*)d_in[5];
    const int*   adj_col = (const int*)d_in[6];
    const int*   hv_row  = (const int*)d_in[7];
    const int*   hv_col  = (const int*)d_in[8];
    const int*   hu_row  = (const int*)d_in[9];
    const int*   hu_col  = (const int*)d_in[10];
    float* out = (float*)d_out;

    const int E_adj = in_sizes[2];
    const int E_hv  = in_sizes[3];
    const int E_hu  = in_sizes[4];

    float *ea, *eb, *bic, *ul;
    cudaGetSymbolAddress((void**)&ea,  g_ea);
    cudaGetSymbolAddress((void**)&eb,  g_eb);
    cudaGetSymbolAddress((void**)&bic, g_bic);
    cudaGetSymbolAddress((void**)&ul,  g_ul);

    const int TB = 256;
    const int ne_tot = E_adj + E_hv + E_hu;

    // ---- CSR build: 5 launches ----
    k_zero_cnt<<<(CNT_TOT + TB - 1) / TB, TB>>>();
    k_hist_all<<<(ne_tot + TB - 1) / TB, TB>>>(adj_row, hv_row, hu_row, E_adj, E_hv, E_hu);
    k_blocksum_all<<<NB_TOT, TB>>>();
    k_scan_chunk_all<<<NB_TOT, TB>>>(E_adj, E_hv, E_hu);
    k_scatter_all<<<(ne_tot + TB - 1) / TB, TB>>>(adj_row, adj_col, adj_val,
                                                  hv_row, hv_col, hv_val,
                                                  hu_row, hu_col, hu_val,
                                                  E_adj, E_hv, E_hu);

    // ---- SpMM: 3 launches ----
    k_phase1<<<(NN + NBIC + 7) / 8, TB>>>(user, item, ea, bic);
    k_phase2<<<(NN + NUM_USERS + 7) / 8, TB>>>(ea, eb, bic, ul);
    k_phase3<<<(NN + 7) / 8, TB>>>(user, item, ea, eb, ul, out);
}